// round 14
// baseline (speedup 1.0000x reference)
#include <cuda_runtime.h>
#include <cstdint>

// Problem constants (fixed by the dataset)
#define N_TOK 4096     // B*K = 128*32
#define DDIM  1024
#define HDIM  256
#define NEXP  32

// Scratch (device globals; no allocation allowed)
__device__ int   g_cnt[NEXP];
__device__ int   g_list[NEXP * N_TOK];
__device__ float g_hidden[N_TOK * HDIM];
__device__ int   g_nwork;
__device__ int   g_work[256];   // max items = sum ceil(cnt/32) <= 128 + 31 = 159

// ---------------------------------------------------------------------------
// cp.async helpers
// ---------------------------------------------------------------------------
__device__ __forceinline__ void cp16(void* dst, const void* src) {
    asm volatile("cp.async.cg.shared.global [%0], [%1], 16;"
                 :: "r"((unsigned)__cvta_generic_to_shared(dst)), "l"(src));
}
__device__ __forceinline__ void cp_commit() {
    asm volatile("cp.async.commit_group;");
}
__device__ __forceinline__ void cp_wait0() {
    asm volatile("cp.async.wait_group 0;");
}

// tf32 high-part mask: keep sign+exp+10 mantissa bits (the 19 bits HW reads)
#define TF32_MASK 0xFFFFE000u

// ---------------------------------------------------------------------------
// Zero counters
// ---------------------------------------------------------------------------
__global__ void zero_kernel() {
    int t = threadIdx.x;
    if (t < NEXP) g_cnt[t] = 0;
    if (t == 0)  g_nwork = 0;
}

// ---------------------------------------------------------------------------
// Router: one warp per token. logits = x @ Wr^T + br ; argmax (first max wins)
// ---------------------------------------------------------------------------
__global__ __launch_bounds__(256) void router_kernel(
    const float* __restrict__ x,
    const float* __restrict__ rw,
    const float* __restrict__ rb)
{
    int gwarp = (blockIdx.x * blockDim.x + threadIdx.x) >> 5;
    int lane  = threadIdx.x & 31;
    if (gwarp >= N_TOK) return;

    const float4* x4 = (const float4*)(x + (size_t)gwarp * DDIM);

    float best = -1e30f;
    int   bidx = 0;
#pragma unroll 1
    for (int e = 0; e < NEXP; e++) {
        const float4* w4 = (const float4*)(rw + (size_t)e * DDIM);
        float s = 0.f;
#pragma unroll
        for (int k = lane; k < DDIM / 4; k += 32) {
            float4 a = x4[k], b = w4[k];
            s += a.x * b.x + a.y * b.y + a.z * b.z + a.w * b.w;
        }
#pragma unroll
        for (int o = 16; o; o >>= 1) s += __shfl_xor_sync(0xffffffffu, s, o);
        s += rb[e];
        if (s > best) { best = s; bidx = e; }   // strict > : first index wins ties
    }
    if (lane == 0) {
        int pos = atomicAdd(&g_cnt[bidx], 1);
        g_list[bidx * N_TOK + pos] = gwarp;
    }
}

// ---------------------------------------------------------------------------
// Build (expert, row_tile) worklist. Tile height = 32 rows.
// ---------------------------------------------------------------------------
__global__ void build_work_kernel() {
    int e = threadIdx.x;
    if (e < NEXP) {
        int nt = (g_cnt[e] + 31) >> 5;
        if (nt > 0) {
            int pos = atomicAdd(&g_nwork, nt);
            for (int i = 0; i < nt; i++) g_work[pos + i] = (e << 16) | i;
        }
    }
}

// ---------------------------------------------------------------------------
// Gathered GEMM + bias + ReLU via 3xTF32 mma.sync.m16n8k8.
//   C[m,n] = relu( sum_k A[tok[m],k] * W[e,k,n] + bias[e,n] )
// Measured (R11): raw-bit tf32 operands => HW truncation, rel_err 1.39e-3.
// Fix: exact split a = ah + al (ah = bits & 0xFFFFE000, al exact fp32
// residual); a*b ~= ah*bh + ah*bl + al*bh, dropping only al*bl ~ 2^-22.
// Restores ~1e-6 accuracy at 3x tensor ops (tensor pipe was idle headroom).
// CTA: 128 threads (4 warps). Tile 32x128, K-step 32, cp.async double-buffer.
// ---------------------------------------------------------------------------
template <int KDIM, int NTOTAL>
__global__ __launch_bounds__(128) void moe_mma_kernel(
    const float* __restrict__ A,     // token-major activations, row stride = KDIM
    const float* __restrict__ W,     // [E, KDIM, NTOTAL]
    const float* __restrict__ Bv,    // [E, NTOTAL]
    float* __restrict__ Out)         // token-major, row stride = NTOTAL
{
    constexpr int NCT    = NTOTAL / 128;   // column tiles of 128
    constexpr int NSTEPS = KDIM / 32;

    __shared__ __align__(16) float As[2][32][36];   // [buf][m][k], stride 36 (144B = 9*16)
    __shared__ __align__(16) float Bs[2][32][132];  // [buf][k][n], stride 132 (528B = 33*16)
    __shared__ int   toks[32];

    const int tid  = threadIdx.x;
    const int warp = tid >> 5;
    const int lane = tid & 31;
    const int mw   = warp & 1;             // warp m-row (0/1)
    const int nw   = warp >> 1;            // warp n-col (0/1)
    const int mb   = mw << 4;              // 0 or 16
    const int nb   = nw << 6;              // 0 or 64
    const int grp  = lane >> 2;            // groupID (0..7)
    const int qid  = lane & 3;             // threadID_in_group

    // A staging: thread covers row am, k ak..ak+7 (2 x 16B)
    const int am = tid >> 2;               // 0..31
    const int ak = (tid & 3) << 3;         // 0,8,16,24
    // B staging: thread covers row bk, cols bc..bc+31 (8 x 16B)
    const int bk = tid & 31;               // 0..31
    const int bc = (tid >> 5) << 5;        // 0,32,64,96

    const int nwork = g_nwork;
    const int total = nwork * NCT;

    for (int w = blockIdx.x; w < total; w += gridDim.x) {
        const int item = g_work[w / NCT];
        const int ct   = w - (w / NCT) * NCT;
        const int e    = item >> 16;
        const int r0   = (item & 0xffff) << 5;
        const int cnt  = g_cnt[e];
        const int n0   = ct << 7;

        if (tid < 32) {
            int idx = r0 + tid;
            if (idx >= cnt) idx = cnt - 1;       // clamp (loads safe, stores guarded)
            toks[tid] = g_list[e * N_TOK + idx];
        }
        __syncthreads();

        const float* Abase = A + (size_t)toks[am] * KDIM + ak;
        const float* Wsrc  = W + (size_t)e * KDIM * NTOTAL + n0;

        // ---- prologue: stage tile 0 into buf 0 ----
        {
            cp16(&As[0][am][ak],     Abase);
            cp16(&As[0][am][ak + 4], Abase + 4);
            const float* bsrc = Wsrc + (size_t)bk * NTOTAL + bc;
#pragma unroll
            for (int i = 0; i < 8; i++)
                cp16(&Bs[0][bk][bc + 4 * i], bsrc + 4 * i);
            cp_commit();
        }

        float acc[8][4];
#pragma unroll
        for (int f = 0; f < 8; f++)
#pragma unroll
            for (int j = 0; j < 4; j++) acc[f][j] = 0.f;

#pragma unroll 1
        for (int step = 0; step < NSTEPS; step++) {
            const int cur = step & 1;

            cp_wait0();
            __syncthreads();   // tile `step` visible; all warps done reading other buf

            if (step + 1 < NSTEPS) {
                const int k0n = (step + 1) << 5;
                const int nxt = cur ^ 1;
                cp16(&As[nxt][am][ak],     Abase + k0n);
                cp16(&As[nxt][am][ak + 4], Abase + k0n + 4);
                const float* bsrc = Wsrc + (size_t)(k0n + bk) * NTOTAL + bc;
#pragma unroll
                for (int i = 0; i < 8; i++)
                    cp16(&Bs[nxt][bk][bc + 4 * i], bsrc + 4 * i);
                cp_commit();
            }

            // ---- compute: 4 k8-substeps x 8 n-frags x 3 mma (3xTF32) ----
#pragma unroll
            for (int ks = 0; ks < 4; ks++) {
                const int k8 = ks << 3;
                float af[4];
                af[0] = As[cur][mb + grp    ][k8 + qid];
                af[1] = As[cur][mb + grp + 8][k8 + qid];
                af[2] = As[cur][mb + grp    ][k8 + qid + 4];
                af[3] = As[cur][mb + grp + 8][k8 + qid + 4];
                unsigned ah[4], al[4];
#pragma unroll
                for (int i = 0; i < 4; i++) {
                    ah[i] = __float_as_uint(af[i]) & TF32_MASK;
                    al[i] = __float_as_uint(af[i] - __uint_as_float(ah[i]));
                }
#pragma unroll
                for (int nf = 0; nf < 8; nf++) {
                    const float* bp = &Bs[cur][k8 + qid][nb + (nf << 3) + grp];
                    float b0f = bp[0];
                    float b1f = bp[4 * 132];
                    unsigned bh0 = __float_as_uint(b0f) & TF32_MASK;
                    unsigned bh1 = __float_as_uint(b1f) & TF32_MASK;
                    unsigned bl0 = __float_as_uint(b0f - __uint_as_float(bh0));
                    unsigned bl1 = __float_as_uint(b1f - __uint_as_float(bh1));
                    // acc += al*bh  (residual-A term)
                    asm volatile(
                        "mma.sync.aligned.m16n8k8.row.col.f32.tf32.tf32.f32 "
                        "{%0,%1,%2,%3}, {%4,%5,%6,%7}, {%8,%9}, {%0,%1,%2,%3};\n"
                        : "+f"(acc[nf][0]), "+f"(acc[nf][1]),
                          "+f"(acc[nf][2]), "+f"(acc[nf][3])
                        : "r"(al[0]), "r"(al[1]), "r"(al[2]), "r"(al[3]),
                          "r"(bh0), "r"(bh1));
                    // acc += ah*bl  (residual-B term)
                    asm volatile(
                        "mma.sync.aligned.m16n8k8.row.col.f32.tf32.tf32.f32 "
                        "{%0,%1,%2,%3}, {%4,%5,%6,%7}, {%8,%9}, {%0,%1,%2,%3};\n"
                        : "+f"(acc[nf][0]), "+f"(acc[nf][1]),
                          "+f"(acc[nf][2]), "+f"(acc[nf][3])
                        : "r"(ah[0]), "r"(ah[1]), "r"(ah[2]), "r"(ah[3]),
                          "r"(bl0), "r"(bl1));
                    // acc += ah*bh  (main term)
                    asm volatile(
                        "mma.sync.aligned.m16n8k8.row.col.f32.tf32.tf32.f32 "
                        "{%0,%1,%2,%3}, {%4,%5,%6,%7}, {%8,%9}, {%0,%1,%2,%3};\n"
                        : "+f"(acc[nf][0]), "+f"(acc[nf][1]),
                          "+f"(acc[nf][2]), "+f"(acc[nf][3])
                        : "r"(ah[0]), "r"(ah[1]), "r"(ah[2]), "r"(ah[3]),
                          "r"(bh0), "r"(bh1));
                }
            }
        }

        // ---- epilogue: bias + ReLU, scatter to token rows ----
        const int m0 = mb + grp, m1 = m0 + 8;
        const int t0 = toks[m0], t1 = toks[m1];
        const bool v0 = (r0 + m0 < cnt), v1 = (r0 + m1 < cnt);
#pragma unroll
        for (int nf = 0; nf < 8; nf++) {
            const int colb = nb + (nf << 3) + (qid << 1);
            float2 bv = *(const float2*)(Bv + (size_t)e * NTOTAL + n0 + colb);
            if (v0) {
                float2 o;
                o.x = fmaxf(acc[nf][0] + bv.x, 0.f);
                o.y = fmaxf(acc[nf][1] + bv.y, 0.f);
                *(float2*)(Out + (size_t)t0 * NTOTAL + n0 + colb) = o;
            }
            if (v1) {
                float2 o;
                o.x = fmaxf(acc[nf][2] + bv.x, 0.f);
                o.y = fmaxf(acc[nf][3] + bv.y, 0.f);
                *(float2*)(Out + (size_t)t1 * NTOTAL + n0 + colb) = o;
            }
        }
        __syncthreads();   // protect toks/smem before next work item
    }
}

// ---------------------------------------------------------------------------
// Launch
// ---------------------------------------------------------------------------
extern "C" void kernel_launch(void* const* d_in, const int* in_sizes, int n_in,
                              void* d_out, int out_size)
{
    const float* x  = (const float*)d_in[0];  // [N, D]
    const float* rw = (const float*)d_in[1];  // [E, D]
    const float* rb = (const float*)d_in[2];  // [E]
    const float* w1 = (const float*)d_in[3];  // [E, D, H]
    const float* b1 = (const float*)d_in[4];  // [E, H]
    const float* w2 = (const float*)d_in[5];  // [E, H, D]
    const float* b2 = (const float*)d_in[6];  // [E, D]
    float* out = (float*)d_out;               // [N, D]

    float* hidden = nullptr;
    cudaGetSymbolAddress((void**)&hidden, g_hidden);

    zero_kernel<<<1, 64>>>();
    router_kernel<<<N_TOK / 8, 256>>>(x, rw, rb);   // 8 warps/block, 1 token/warp
    build_work_kernel<<<1, 32>>>();
    // layer 1: K=D=1024 -> H=256 (2 col tiles of 128). Max items*NCT = 159*2 = 318.
    moe_mma_kernel<DDIM, HDIM><<<320, 128>>>(x, w1, b1, hidden);
    // layer 2: K=H=256 -> D=1024 (8 col tiles of 128). Max items*NCT = 159*8 = 1272.
    moe_mma_kernel<HDIM, DDIM><<<1280, 128>>>(hidden, w2, b2, out);
}